// round 15
// baseline (speedup 1.0000x reference)
#include <cuda_runtime.h>
#include <cuda_fp16.h>
#include <math.h>

#define H 64
#define NB 8
#define NL 2
#define MAXN 50000
#define MAXE 800000

// ---------------- scratch (device globals; no allocation allowed) ------------
__device__ __align__(256) float  g_x[MAXN * H];
__device__ __align__(256) __half g_Ph[MAXN * H];    // x@W1a + b1 (fp16)
__device__ __align__(256) __half g_Qh[MAXN * H];    // x@W1b      (fp16)
__device__ __align__(256) __half g_aggHh[MAXN * H]; // fp16 accumulator
__device__ __align__(256) __half g_eah[MAXE * NB];  // edge attrs (fp16)
__device__ __align__(256) int2   g_eidx[MAXE];      // packed (row, col)
__device__ __align__(256) float  g_deg[MAXN];
__device__ __align__(256) float4 g_pos4[MAXN];      // packed positions

__device__ __forceinline__ float silu(float v) {
    return __fdividef(v, 1.0f + __expf(-v));
}

__device__ __forceinline__ unsigned h2_to_u(__half2 h) {
    return *reinterpret_cast<unsigned*>(&h);
}
__device__ __forceinline__ float2 u_to_f2(unsigned u) {
    __half2 h = *reinterpret_cast<__half2*>(&u);
    return __half22float2(h);
}

// ---------------- zero deg + out; pack pos into float4 -------------------------
__global__ void k_prep(const float* __restrict__ pos, int N,
                       float* __restrict__ deg, float* __restrict__ out, int nout) {
    int i = blockIdx.x * blockDim.x + threadIdx.x;
    int stride = gridDim.x * blockDim.x;
    for (int t = i; t < N; t += stride) {
        deg[t] = 0.0f;
        g_pos4[t] = make_float4(pos[t * 3 + 0], pos[t * 3 + 1], pos[t * 3 + 2], 0.0f);
    }
    for (int t = i; t < nout; t += stride) out[t] = 0.0f;
}

// ---------------- edge_attr (fp16) + degree + packed index ---------------------
__global__ void k_edge_attr(const int* __restrict__ ei, int E) {
    int e = blockIdx.x * blockDim.x + threadIdx.x;
    int stride = gridDim.x * blockDim.x;
    const float PI = 3.14159265358979323846f;
    uint4* ea4 = (uint4*)g_eah;
    for (; e < E; e += stride) {
        int r = __ldg(&ei[e]), c = __ldg(&ei[E + e]);
        g_eidx[e] = make_int2(r, c);
        float4 pr = __ldg(&g_pos4[r]);
        float4 pc = __ldg(&g_pos4[c]);
        float dx = pr.x - pc.x;
        float dy = pr.y - pc.y;
        float dz = pr.z - pc.z;
        float d = sqrtf(dx * dx + dy * dy + dz * dz);
        float env = 0.0f;
        if (d < 5.0f) {
            float cv = __cosf(d * (PI / 10.0f));
            env = cv * cv;
        }
        float inv = __fdividef(env, (d > 0.0f) ? d : 1.0f);
        float s1, c1;
        __sincosf(d * (PI / 5.0f), &s1, &c1);
        float twoc = 2.0f * c1;
        float sp = 0.0f, sc = s1;   // sin(k*theta) recurrence
        float v[NB];
#pragma unroll
        for (int j = 0; j < NB; j++) {
            v[j] = sc * inv;
            float sn = twoc * sc - sp;
            sp = sc; sc = sn;
        }
        uint4 u;
        u.x = h2_to_u(__floats2half2_rn(v[0], v[1]));
        u.y = h2_to_u(__floats2half2_rn(v[2], v[3]));
        u.z = h2_to_u(__floats2half2_rn(v[4], v[5]));
        u.w = h2_to_u(__floats2half2_rn(v[6], v[7]));
        ea4[e] = u;
        atomicAdd(&g_deg[c], 1.0f);
    }
}

// ---------------- P = x@W1a + b1, Q = x@W1b (fp16 out); zero aggH; opt gather ---
// weights in smem as half2 (16KB) -> 6 blocks/SM; lane l<16: P cols, l>=16: Q cols
__global__ void __launch_bounds__(256, 6)
k_pq(const float* __restrict__ w1, const float* __restrict__ b1,
     const int* __restrict__ z, const float* __restrict__ embed, int N) {
    __shared__ uint2 sB2[64 * 32];   // [k][lane] : 4 fp16 cols per entry
    __shared__ float4 sb1[16];
    __shared__ float4 sA4[8][64];    // 4 rows x 16 f4 per warp

    const float4* w1v = (const float4*)w1;
    for (int u = threadIdx.x; u < 64 * 32; u += blockDim.x) {
        int k = u >> 5, l = u & 31;
        float4 f = (l < 16) ? w1v[k * 16 + l] : w1v[(64 + k) * 16 + (l - 16)];
        sB2[u] = make_uint2(h2_to_u(__floats2half2_rn(f.x, f.y)),
                            h2_to_u(__floats2half2_rn(f.z, f.w)));
    }
    if (threadIdx.x < 16) sb1[threadIdx.x] = ((const float4*)b1)[threadIdx.x];
    __syncthreads();

    int warp = threadIdx.x >> 5, lane = threadIdx.x & 31;
    int gw = (blockIdx.x * blockDim.x + threadIdx.x) >> 5;
    int nw = (gridDim.x * blockDim.x) >> 5;

    uint2* P2 = (uint2*)g_Ph;    // per node: 16 uint2 (4 halves each)
    uint2* Q2 = (uint2*)g_Qh;
    uint2* Z2 = (uint2*)g_aggHh; // per node: 16 uint2 (fp16 zero fill)
    float4* X4 = (float4*)g_x;
    const float4* E4 = (const float4*)embed;
    float* sA = (float*)sA4[warp];

    bool gather = (z != nullptr);

    for (int r0 = gw * 4; r0 < N; r0 += nw * 4) {
        int nr = min(4, N - r0);
        if (gather) {
            for (int t = lane; t < nr * 16; t += 32) {
                int rr = t >> 4, cc = t & 15;
                float4 v = E4[(size_t)__ldg(&z[r0 + rr]) * 16 + cc];
                sA4[warp][t] = v;
                X4[(size_t)(r0 + rr) * 16 + cc] = v;
            }
        } else {
            for (int t = lane; t < nr * 16; t += 32)
                sA4[warp][t] = X4[(size_t)r0 * 16 + t];
        }
        __syncwarp();

        float4 acc[4];
#pragma unroll
        for (int rr = 0; rr < 4; rr++)
            acc[rr] = (lane < 16) ? sb1[lane & 15] : make_float4(0.f, 0.f, 0.f, 0.f);

#pragma unroll 8
        for (int k = 0; k < 64; k++) {
            uint2 bu = sB2[k * 32 + lane];
            float2 b01 = u_to_f2(bu.x);
            float2 b23 = u_to_f2(bu.y);
#pragma unroll
            for (int rr = 0; rr < 4; rr++) {
                float a = sA[rr * 64 + k];
                acc[rr].x = fmaf(a, b01.x, acc[rr].x);
                acc[rr].y = fmaf(a, b01.y, acc[rr].y);
                acc[rr].z = fmaf(a, b23.x, acc[rr].z);
                acc[rr].w = fmaf(a, b23.y, acc[rr].w);
            }
        }
        for (int rr = 0; rr < nr; rr++) {
            size_t b = (size_t)(r0 + rr) * 16;
            uint2 u;
            u.x = h2_to_u(__floats2half2_rn(acc[rr].x, acc[rr].y));
            u.y = h2_to_u(__floats2half2_rn(acc[rr].z, acc[rr].w));
            if (lane < 16) {
                P2[b + lane] = u;
                Z2[b + lane] = make_uint2(0u, 0u);
            } else {
                Q2[b + (lane - 16)] = u;
            }
        }
        __syncwarp();
    }
}

// ---------------- edge phase: aggH[c] += silu(P[c]+Q[r]+ea@W1c) ----------------
// half-warp per edge; lane covers 4 output cols; fp16x2 vector reduction
__global__ void __launch_bounds__(256, 8)
k_edge(const float* __restrict__ w1, int E) {
    __shared__ float4 sWc[NB * 16];
    const float4* wc = (const float4*)(w1 + 128 * 64);
    for (int u = threadIdx.x; u < NB * 16; u += blockDim.x) sWc[u] = wc[u];
    __syncthreads();

    int lane = threadIdx.x & 31;
    int half = lane >> 4;
    int hl = lane & 15;
    int gw = (blockIdx.x * blockDim.x + threadIdx.x) >> 5;
    int nw = (gridDim.x * blockDim.x) >> 5;

    const uint2* P2 = (const uint2*)g_Ph;
    const uint2* Q2 = (const uint2*)g_Qh;
    const uint4* ea4 = (const uint4*)g_eah;

    for (int e0 = gw * 2; e0 < E; e0 += nw * 2) {
        int e = e0 + half;
        if (e < E) {
            int2 rc = __ldg(&g_eidx[e]);
            int r = rc.x, c = rc.y;
            uint2 up = __ldg(&P2[(size_t)c * 16 + hl]);
            uint2 uq = __ldg(&Q2[(size_t)r * 16 + hl]);
            uint4 ue = __ldg(&ea4[e]);

            float4 v;
            {
                float2 p = u_to_f2(up.x);
                float2 q = u_to_f2(uq.x);
                v.x = p.x + q.x; v.y = p.y + q.y;
                p = u_to_f2(up.y);
                q = u_to_f2(uq.y);
                v.z = p.x + q.x; v.w = p.y + q.y;
            }
            {
                float2 ee = u_to_f2(ue.x);
                float4 w = sWc[0 * 16 + hl];
                v.x = fmaf(ee.x, w.x, v.x); v.y = fmaf(ee.x, w.y, v.y);
                v.z = fmaf(ee.x, w.z, v.z); v.w = fmaf(ee.x, w.w, v.w);
                w = sWc[1 * 16 + hl];
                v.x = fmaf(ee.y, w.x, v.x); v.y = fmaf(ee.y, w.y, v.y);
                v.z = fmaf(ee.y, w.z, v.z); v.w = fmaf(ee.y, w.w, v.w);
            }
            {
                float2 ee = u_to_f2(ue.y);
                float4 w = sWc[2 * 16 + hl];
                v.x = fmaf(ee.x, w.x, v.x); v.y = fmaf(ee.x, w.y, v.y);
                v.z = fmaf(ee.x, w.z, v.z); v.w = fmaf(ee.x, w.w, v.w);
                w = sWc[3 * 16 + hl];
                v.x = fmaf(ee.y, w.x, v.x); v.y = fmaf(ee.y, w.y, v.y);
                v.z = fmaf(ee.y, w.z, v.z); v.w = fmaf(ee.y, w.w, v.w);
            }
            {
                float2 ee = u_to_f2(ue.z);
                float4 w = sWc[4 * 16 + hl];
                v.x = fmaf(ee.x, w.x, v.x); v.y = fmaf(ee.x, w.y, v.y);
                v.z = fmaf(ee.x, w.z, v.z); v.w = fmaf(ee.x, w.w, v.w);
                w = sWc[5 * 16 + hl];
                v.x = fmaf(ee.y, w.x, v.x); v.y = fmaf(ee.y, w.y, v.y);
                v.z = fmaf(ee.y, w.z, v.z); v.w = fmaf(ee.y, w.w, v.w);
            }
            {
                float2 ee = u_to_f2(ue.w);
                float4 w = sWc[6 * 16 + hl];
                v.x = fmaf(ee.x, w.x, v.x); v.y = fmaf(ee.x, w.y, v.y);
                v.z = fmaf(ee.x, w.z, v.z); v.w = fmaf(ee.x, w.w, v.w);
                w = sWc[7 * 16 + hl];
                v.x = fmaf(ee.y, w.x, v.x); v.y = fmaf(ee.y, w.y, v.y);
                v.z = fmaf(ee.y, w.z, v.z); v.w = fmaf(ee.y, w.w, v.w);
            }

            unsigned m01 = h2_to_u(__floats2half2_rn(silu(v.x), silu(v.y)));
            unsigned m23 = h2_to_u(__floats2half2_rn(silu(v.z), silu(v.w)));
            __half* dst = g_aggHh + (size_t)c * 64 + hl * 4;
            asm volatile("red.global.add.noftz.v2.f16x2 [%0], {%1, %2};"
                         :: "l"(dst), "r"(m01), "r"(m23) : "memory");
        }
    }
}

// ---------------- fused node phase (half2 weights; interleaved staging) --------
__global__ void __launch_bounds__(256, 4)
k_node(const float* __restrict__ w2, const float* __restrict__ b2,
       const float* __restrict__ uw1, const float* __restrict__ ub1,
       const float* __restrict__ uw2, const float* __restrict__ ub2,
       const float* __restrict__ ew1, const float* __restrict__ eb1,
       const float* __restrict__ ew2, const float* __restrict__ eb2,
       const int* __restrict__ batch, float* __restrict__ out,
       int N, int do_readout) {
    extern __shared__ float sm[];
    unsigned* uW2  = (unsigned*)sm;               // 2048 u32 (half2)
    unsigned* uUW1 = uW2 + 2048;                  // 4096
    unsigned* uUW2 = uUW1 + 4096;                 // 2048
    unsigned* uEW1 = uUW2 + 2048;                 // 2048  (ends at 10240 words)
    float2* sb2v  = (float2*)(sm + 10240);        // 32 f2
    float2* sub1v = sb2v + 32;
    float2* sub2v = sub1v + 32;
    float2* seb1v = sub2v + 32;
    float2* sew2v = seb1v + 32;                   // ends at 10560 words
    float* sEb2 = sm + 10560;                     // 16 words pad
    float* sIn  = sm + 10576;                     // 8 warps * 256 (128 float2 pairs)
    float* sHid = sm + 12624;                     // 8 warps * 128 (64 float2 pairs)

    for (int u = threadIdx.x; u < 2048; u += blockDim.x) {
        float2 f = ((const float2*)w2)[u];
        uW2[u] = h2_to_u(__floats2half2_rn(f.x, f.y));
    }
    for (int u = threadIdx.x; u < 4096; u += blockDim.x) {
        float2 f = ((const float2*)uw1)[u];
        uUW1[u] = h2_to_u(__floats2half2_rn(f.x, f.y));
    }
    for (int u = threadIdx.x; u < 2048; u += blockDim.x) {
        float2 f = ((const float2*)uw2)[u];
        uUW2[u] = h2_to_u(__floats2half2_rn(f.x, f.y));
    }
    if (do_readout) {
        for (int u = threadIdx.x; u < 2048; u += blockDim.x) {
            float2 f = ((const float2*)ew1)[u];
            uEW1[u] = h2_to_u(__floats2half2_rn(f.x, f.y));
        }
    }
    if (threadIdx.x < 32) {
        sb2v[threadIdx.x]  = ((const float2*)b2)[threadIdx.x];
        sub1v[threadIdx.x] = ((const float2*)ub1)[threadIdx.x];
        sub2v[threadIdx.x] = ((const float2*)ub2)[threadIdx.x];
        if (do_readout) {
            seb1v[threadIdx.x] = ((const float2*)eb1)[threadIdx.x];
            sew2v[threadIdx.x] = ((const float2*)ew2)[threadIdx.x];
        }
    }
    if (threadIdx.x == 0) sEb2[0] = do_readout ? eb2[0] : 0.0f;
    __syncthreads();

    int warp = threadIdx.x >> 5, lane = threadIdx.x & 31;
    int gw = (blockIdx.x * blockDim.x + threadIdx.x) >> 5;
    int nw = (gridDim.x * blockDim.x) >> 5;
    float2* inP  = (float2*)(sIn + warp * 256);   // 128 pairs
    float2* hidP = (float2*)(sHid + warp * 128);  // 64 pairs

    const float2* X2r = (const float2*)g_x;
    float2* X2w = (float2*)g_x;
    const unsigned* AGH = (const unsigned*)g_aggHh;   // fp16x2 accumulators

    for (int r0 = gw * 2; r0 < N; r0 += nw * 2) {
        int nr = min(2, N - r0);

        // --- phase A: agg = aggH @ W2 + deg*b2 (interleaved pairs) ---
        {
            float2 ag0 = u_to_f2(AGH[(size_t)r0 * 32 + lane]);
            float2 ag1 = (nr > 1) ? u_to_f2(AGH[(size_t)(r0 + 1) * 32 + lane])
                                  : make_float2(0.f, 0.f);
            hidP[2 * lane]     = make_float2(ag0.x, ag1.x);
            hidP[2 * lane + 1] = make_float2(ag0.y, ag1.y);
        }
        __syncwarp();

        float2 agg[2] = {make_float2(0.f, 0.f), make_float2(0.f, 0.f)};
#pragma unroll 8
        for (int k = 0; k < 64; k++) {
            float2 a = hidP[k];                       // (row0[k], row1[k])
            float2 b = u_to_f2(uW2[k * 32 + lane]);
            agg[0].x = fmaf(a.x, b.x, agg[0].x); agg[0].y = fmaf(a.x, b.y, agg[0].y);
            agg[1].x = fmaf(a.y, b.x, agg[1].x); agg[1].y = fmaf(a.y, b.y, agg[1].y);
        }
        float2 bb2 = sb2v[lane];
        float2 xp[2], nx[2];
        nx[0] = nx[1] = make_float2(0.f, 0.f);
#pragma unroll
        for (int rr = 0; rr < 2; rr++) {
            float dg = (rr < nr) ? g_deg[r0 + rr] : 0.0f;
            agg[rr].x = fmaf(dg, bb2.x, agg[rr].x);
            agg[rr].y = fmaf(dg, bb2.y, agg[rr].y);
            if (rr < nr) xp[rr] = X2r[(r0 + rr) * 32 + lane];
            else         xp[rr] = make_float2(0.f, 0.f);
        }
        __syncwarp();

        // --- phase B: stage [x, agg] interleaved ---
        inP[2 * lane]          = make_float2(xp[0].x, xp[1].x);
        inP[2 * lane + 1]      = make_float2(xp[0].y, xp[1].y);
        inP[64 + 2 * lane]     = make_float2(agg[0].x, agg[1].x);
        inP[64 + 2 * lane + 1] = make_float2(agg[0].y, agg[1].y);
        __syncwarp();

        // --- phase C: hidden = silu([x,agg]@uW1 + ub1) ---
        float2 ub1p = sub1v[lane];
        float2 acc[2] = {ub1p, ub1p};
#pragma unroll 8
        for (int k = 0; k < 128; k++) {
            float2 a = inP[k];
            float2 w = u_to_f2(uUW1[k * 32 + lane]);
            acc[0].x = fmaf(a.x, w.x, acc[0].x); acc[0].y = fmaf(a.x, w.y, acc[0].y);
            acc[1].x = fmaf(a.y, w.x, acc[1].x); acc[1].y = fmaf(a.y, w.y, acc[1].y);
        }
        __syncwarp();
        hidP[2 * lane]     = make_float2(silu(acc[0].x), silu(acc[1].x));
        hidP[2 * lane + 1] = make_float2(silu(acc[0].y), silu(acc[1].y));
        __syncwarp();

        // --- phase D: o = hid@uW2 + ub2; x += o ---
        float2 ub2p = sub2v[lane];
        float2 o[2] = {ub2p, ub2p};
#pragma unroll 8
        for (int k = 0; k < 64; k++) {
            float2 a = hidP[k];
            float2 w = u_to_f2(uUW2[k * 32 + lane]);
            o[0].x = fmaf(a.x, w.x, o[0].x); o[0].y = fmaf(a.x, w.y, o[0].y);
            o[1].x = fmaf(a.y, w.x, o[1].x); o[1].y = fmaf(a.y, w.y, o[1].y);
        }
        for (int rr = 0; rr < nr; rr++) {
            nx[rr].x = xp[rr].x + o[rr].x;
            nx[rr].y = xp[rr].y + o[rr].y;
            X2w[(r0 + rr) * 32 + lane] = nx[rr];
        }

        // --- phase E: readout (last layer only) ---
        if (do_readout) {
            __syncwarp();
            inP[2 * lane]     = make_float2(nx[0].x, nx[1].x);
            inP[2 * lane + 1] = make_float2(nx[0].y, nx[1].y);
            __syncwarp();
            float2 eb1p = seb1v[lane];
            float2 ec[2] = {eb1p, eb1p};
#pragma unroll 8
            for (int k = 0; k < 64; k++) {
                float2 a = inP[k];
                float2 w = u_to_f2(uEW1[k * 32 + lane]);
                ec[0].x = fmaf(a.x, w.x, ec[0].x); ec[0].y = fmaf(a.x, w.y, ec[0].y);
                ec[1].x = fmaf(a.y, w.x, ec[1].x); ec[1].y = fmaf(a.y, w.y, ec[1].y);
            }
            float2 w2p = sew2v[lane];
            for (int rr = 0; rr < nr; rr++) {
                float pe = silu(ec[rr].x) * w2p.x + silu(ec[rr].y) * w2p.y;
#pragma unroll
                for (int off = 16; off > 0; off >>= 1)
                    pe += __shfl_xor_sync(0xFFFFFFFF, pe, off);
                if (lane == 0)
                    atomicAdd(&out[batch[r0 + rr]], pe + sEb2[0]);
            }
        }
        __syncwarp();
    }
}

// ------------------------------- host side ------------------------------------
extern "C" void kernel_launch(void* const* d_in, const int* in_sizes, int n_in,
                              void* d_out, int out_size) {
    const int* z = (const int*)d_in[0];
    const float* pos = (const float*)d_in[1];
    const int* ei = (const int*)d_in[2];
    const int* batch = (const int*)d_in[3];
    const float* embed = (const float*)d_in[4];
    const float* msg_w1 = (const float*)d_in[5];
    const float* msg_b1 = (const float*)d_in[6];
    const float* msg_w2 = (const float*)d_in[7];
    const float* msg_b2 = (const float*)d_in[8];
    const float* upd_w1 = (const float*)d_in[9];
    const float* upd_b1 = (const float*)d_in[10];
    const float* upd_w2 = (const float*)d_in[11];
    const float* upd_b2 = (const float*)d_in[12];
    const float* eh_w1 = (const float*)d_in[13];
    const float* eh_b1 = (const float*)d_in[14];
    const float* eh_w2 = (const float*)d_in[15];
    const float* eh_b2 = (const float*)d_in[16];
    float* out = (float*)d_out;

    int N = in_sizes[0];
    int E = in_sizes[2] / 2;

    float* p_deg; cudaGetSymbolAddress((void**)&p_deg, g_deg);

    static bool init_done = false;
    static cudaStream_t s2;
    static cudaEvent_t ev_fork, ev_join;
    if (!init_done) {
        cudaFuncSetAttribute(k_node, cudaFuncAttributeMaxDynamicSharedMemorySize, 13648 * 4);
        cudaStreamCreateWithFlags(&s2, cudaStreamNonBlocking);
        cudaEventCreateWithFlags(&ev_fork, cudaEventDisableTiming);
        cudaEventCreateWithFlags(&ev_join, cudaEventDisableTiming);
        init_done = true;
    }

    const int TPB = 256;
    const int PQB  = 148 * 6;   // one full resident wave for k_pq (6 blocks/SM)
    const int EBLK = 148 * 8;   // one full resident wave for k_edge (8 blocks/SM)
    const int NODB = 148 * 4;   // one full resident wave for k_node (4 blocks/SM)

    // fork: k_pq(layer0, embed gather) runs concurrently with prep + edge_attr
    cudaEventRecord(ev_fork, 0);
    cudaStreamWaitEvent(s2, ev_fork, 0);
    k_pq<<<PQB, TPB, 0, s2>>>(msg_w1, msg_b1, z, embed, N);
    cudaEventRecord(ev_join, s2);

    k_prep<<<256, TPB>>>(pos, N, p_deg, out, out_size);
    k_edge_attr<<<1184, TPB>>>(ei, E);
    cudaStreamWaitEvent(0, ev_join, 0);

    for (int l = 0; l < NL; l++) {
        const float* w1 = msg_w1 + l * 136 * 64;
        const float* b1 = msg_b1 + l * 64;
        const float* w2 = msg_w2 + l * 64 * 64;
        const float* b2 = msg_b2 + l * 64;
        const float* uw1 = upd_w1 + l * 128 * 64;
        const float* ub1 = upd_b1 + l * 64;
        const float* uw2 = upd_w2 + l * 64 * 64;
        const float* ub2 = upd_b2 + l * 64;

        if (l > 0)
            k_pq<<<PQB, TPB>>>(w1, b1, nullptr, nullptr, N);
        k_edge<<<EBLK, TPB>>>(w1, E);
        k_node<<<NODB, TPB, 13648 * 4>>>(w2, b2, uw1, ub1, uw2, ub2,
                                         eh_w1, eh_b1, eh_w2, eh_b2,
                                         batch, out, N, (l == NL - 1) ? 1 : 0);
    }
}

// round 16
// speedup vs baseline: 1.0193x; 1.0193x over previous
#include <cuda_runtime.h>
#include <cuda_fp16.h>
#include <math.h>

#define H 64
#define NB 8
#define NL 2
#define MAXN 50000
#define MAXE 800000

// ---------------- scratch (device globals; no allocation allowed) ------------
__device__ __align__(256) float  g_x[MAXN * H];
__device__ __align__(256) __half g_Ph[MAXN * H];    // x@W1a + b1 (fp16)
__device__ __align__(256) __half g_Qh[MAXN * H];    // x@W1b      (fp16)
__device__ __align__(256) __half g_aggHh[MAXN * H]; // fp16 accumulator
__device__ __align__(256) __half g_eah[MAXE * NB];  // edge attrs (fp16)
__device__ __align__(256) int2   g_eidx[MAXE];      // packed (row, col)
__device__ __align__(256) float  g_deg[MAXN];
__device__ __align__(256) float4 g_pos4[MAXN];      // packed positions

__device__ __forceinline__ float silu(float v) {
    return __fdividef(v, 1.0f + __expf(-v));
}

__device__ __forceinline__ unsigned h2_to_u(__half2 h) {
    return *reinterpret_cast<unsigned*>(&h);
}
__device__ __forceinline__ float2 u_to_f2(unsigned u) {
    __half2 h = *reinterpret_cast<__half2*>(&u);
    return __half22float2(h);
}

// ---------------- zero deg + out; pack pos into float4 -------------------------
__global__ void k_prep(const float* __restrict__ pos, int N,
                       float* __restrict__ deg, float* __restrict__ out, int nout) {
    int i = blockIdx.x * blockDim.x + threadIdx.x;
    int stride = gridDim.x * blockDim.x;
    for (int t = i; t < N; t += stride) {
        deg[t] = 0.0f;
        g_pos4[t] = make_float4(pos[t * 3 + 0], pos[t * 3 + 1], pos[t * 3 + 2], 0.0f);
    }
    for (int t = i; t < nout; t += stride) out[t] = 0.0f;
}

// ---------------- edge_attr (fp16) + degree + packed index ---------------------
__global__ void k_edge_attr(const int* __restrict__ ei, int E) {
    int e = blockIdx.x * blockDim.x + threadIdx.x;
    int stride = gridDim.x * blockDim.x;
    const float PI = 3.14159265358979323846f;
    uint4* ea4 = (uint4*)g_eah;
    for (; e < E; e += stride) {
        int r = __ldg(&ei[e]), c = __ldg(&ei[E + e]);
        g_eidx[e] = make_int2(r, c);
        float4 pr = __ldg(&g_pos4[r]);
        float4 pc = __ldg(&g_pos4[c]);
        float dx = pr.x - pc.x;
        float dy = pr.y - pc.y;
        float dz = pr.z - pc.z;
        float d = sqrtf(dx * dx + dy * dy + dz * dz);
        float env = 0.0f;
        if (d < 5.0f) {
            float cv = __cosf(d * (PI / 10.0f));
            env = cv * cv;
        }
        float inv = __fdividef(env, (d > 0.0f) ? d : 1.0f);
        float s1, c1;
        __sincosf(d * (PI / 5.0f), &s1, &c1);
        float twoc = 2.0f * c1;
        float sp = 0.0f, sc = s1;   // sin(k*theta) recurrence
        float v[NB];
#pragma unroll
        for (int j = 0; j < NB; j++) {
            v[j] = sc * inv;
            float sn = twoc * sc - sp;
            sp = sc; sc = sn;
        }
        uint4 u;
        u.x = h2_to_u(__floats2half2_rn(v[0], v[1]));
        u.y = h2_to_u(__floats2half2_rn(v[2], v[3]));
        u.z = h2_to_u(__floats2half2_rn(v[4], v[5]));
        u.w = h2_to_u(__floats2half2_rn(v[6], v[7]));
        ea4[e] = u;
        atomicAdd(&g_deg[c], 1.0f);
    }
}

// ---------------- P = x@W1a + b1, Q = x@W1b (fp16 out); zero aggH; opt gather ---
// weights in smem as half2 (16KB) -> 6 blocks/SM; lane l<16: P cols, l>=16: Q cols
__global__ void __launch_bounds__(256, 6)
k_pq(const float* __restrict__ w1, const float* __restrict__ b1,
     const int* __restrict__ z, const float* __restrict__ embed, int N) {
    __shared__ uint2 sB2[64 * 32];   // [k][lane] : 4 fp16 cols per entry
    __shared__ float4 sb1[16];
    __shared__ float4 sA4[8][64];    // 4 rows x 16 f4 per warp

    const float4* w1v = (const float4*)w1;
    for (int u = threadIdx.x; u < 64 * 32; u += blockDim.x) {
        int k = u >> 5, l = u & 31;
        float4 f = (l < 16) ? w1v[k * 16 + l] : w1v[(64 + k) * 16 + (l - 16)];
        sB2[u] = make_uint2(h2_to_u(__floats2half2_rn(f.x, f.y)),
                            h2_to_u(__floats2half2_rn(f.z, f.w)));
    }
    if (threadIdx.x < 16) sb1[threadIdx.x] = ((const float4*)b1)[threadIdx.x];
    __syncthreads();

    int warp = threadIdx.x >> 5, lane = threadIdx.x & 31;
    int gw = (blockIdx.x * blockDim.x + threadIdx.x) >> 5;
    int nw = (gridDim.x * blockDim.x) >> 5;

    uint2* P2 = (uint2*)g_Ph;    // per node: 16 uint2 (4 halves each)
    uint2* Q2 = (uint2*)g_Qh;
    uint2* Z2 = (uint2*)g_aggHh; // per node: 16 uint2 (fp16 zero fill)
    float4* X4 = (float4*)g_x;
    const float4* E4 = (const float4*)embed;
    float* sA = (float*)sA4[warp];

    bool gather = (z != nullptr);

    for (int r0 = gw * 4; r0 < N; r0 += nw * 4) {
        int nr = min(4, N - r0);
        if (gather) {
            for (int t = lane; t < nr * 16; t += 32) {
                int rr = t >> 4, cc = t & 15;
                float4 v = E4[(size_t)__ldg(&z[r0 + rr]) * 16 + cc];
                sA4[warp][t] = v;
                X4[(size_t)(r0 + rr) * 16 + cc] = v;
            }
        } else {
            for (int t = lane; t < nr * 16; t += 32)
                sA4[warp][t] = X4[(size_t)r0 * 16 + t];
        }
        __syncwarp();

        float4 acc[4];
#pragma unroll
        for (int rr = 0; rr < 4; rr++)
            acc[rr] = (lane < 16) ? sb1[lane & 15] : make_float4(0.f, 0.f, 0.f, 0.f);

#pragma unroll 8
        for (int k = 0; k < 64; k++) {
            uint2 bu = sB2[k * 32 + lane];
            float2 b01 = u_to_f2(bu.x);
            float2 b23 = u_to_f2(bu.y);
#pragma unroll
            for (int rr = 0; rr < 4; rr++) {
                float a = sA[rr * 64 + k];
                acc[rr].x = fmaf(a, b01.x, acc[rr].x);
                acc[rr].y = fmaf(a, b01.y, acc[rr].y);
                acc[rr].z = fmaf(a, b23.x, acc[rr].z);
                acc[rr].w = fmaf(a, b23.y, acc[rr].w);
            }
        }
        for (int rr = 0; rr < nr; rr++) {
            size_t b = (size_t)(r0 + rr) * 16;
            uint2 u;
            u.x = h2_to_u(__floats2half2_rn(acc[rr].x, acc[rr].y));
            u.y = h2_to_u(__floats2half2_rn(acc[rr].z, acc[rr].w));
            if (lane < 16) {
                P2[b + lane] = u;
                Z2[b + lane] = make_uint2(0u, 0u);
            } else {
                Q2[b + (lane - 16)] = u;
            }
        }
        __syncwarp();
    }
}

// ---------------- edge phase: aggH[c] += silu(P[c]+Q[r]+ea@W1c) ----------------
// half-warp per edge; lane covers 4 output cols; fp16x2 vector reduction
__global__ void __launch_bounds__(256, 8)
k_edge(const float* __restrict__ w1, int E) {
    __shared__ float4 sWc[NB * 16];
    const float4* wc = (const float4*)(w1 + 128 * 64);
    for (int u = threadIdx.x; u < NB * 16; u += blockDim.x) sWc[u] = wc[u];
    __syncthreads();

    int lane = threadIdx.x & 31;
    int half = lane >> 4;
    int hl = lane & 15;
    int gw = (blockIdx.x * blockDim.x + threadIdx.x) >> 5;
    int nw = (gridDim.x * blockDim.x) >> 5;

    const uint2* P2 = (const uint2*)g_Ph;
    const uint2* Q2 = (const uint2*)g_Qh;
    const uint4* ea4 = (const uint4*)g_eah;

    for (int e0 = gw * 2; e0 < E; e0 += nw * 2) {
        int e = e0 + half;
        if (e < E) {
            int2 rc = __ldg(&g_eidx[e]);
            int r = rc.x, c = rc.y;
            uint2 up = __ldg(&P2[(size_t)c * 16 + hl]);
            uint2 uq = __ldg(&Q2[(size_t)r * 16 + hl]);
            uint4 ue = __ldg(&ea4[e]);

            float4 v;
            {
                float2 p = u_to_f2(up.x);
                float2 q = u_to_f2(uq.x);
                v.x = p.x + q.x; v.y = p.y + q.y;
                p = u_to_f2(up.y);
                q = u_to_f2(uq.y);
                v.z = p.x + q.x; v.w = p.y + q.y;
            }
            {
                float2 ee = u_to_f2(ue.x);
                float4 w = sWc[0 * 16 + hl];
                v.x = fmaf(ee.x, w.x, v.x); v.y = fmaf(ee.x, w.y, v.y);
                v.z = fmaf(ee.x, w.z, v.z); v.w = fmaf(ee.x, w.w, v.w);
                w = sWc[1 * 16 + hl];
                v.x = fmaf(ee.y, w.x, v.x); v.y = fmaf(ee.y, w.y, v.y);
                v.z = fmaf(ee.y, w.z, v.z); v.w = fmaf(ee.y, w.w, v.w);
            }
            {
                float2 ee = u_to_f2(ue.y);
                float4 w = sWc[2 * 16 + hl];
                v.x = fmaf(ee.x, w.x, v.x); v.y = fmaf(ee.x, w.y, v.y);
                v.z = fmaf(ee.x, w.z, v.z); v.w = fmaf(ee.x, w.w, v.w);
                w = sWc[3 * 16 + hl];
                v.x = fmaf(ee.y, w.x, v.x); v.y = fmaf(ee.y, w.y, v.y);
                v.z = fmaf(ee.y, w.z, v.z); v.w = fmaf(ee.y, w.w, v.w);
            }
            {
                float2 ee = u_to_f2(ue.z);
                float4 w = sWc[4 * 16 + hl];
                v.x = fmaf(ee.x, w.x, v.x); v.y = fmaf(ee.x, w.y, v.y);
                v.z = fmaf(ee.x, w.z, v.z); v.w = fmaf(ee.x, w.w, v.w);
                w = sWc[5 * 16 + hl];
                v.x = fmaf(ee.y, w.x, v.x); v.y = fmaf(ee.y, w.y, v.y);
                v.z = fmaf(ee.y, w.z, v.z); v.w = fmaf(ee.y, w.w, v.w);
            }
            {
                float2 ee = u_to_f2(ue.w);
                float4 w = sWc[6 * 16 + hl];
                v.x = fmaf(ee.x, w.x, v.x); v.y = fmaf(ee.x, w.y, v.y);
                v.z = fmaf(ee.x, w.z, v.z); v.w = fmaf(ee.x, w.w, v.w);
                w = sWc[7 * 16 + hl];
                v.x = fmaf(ee.y, w.x, v.x); v.y = fmaf(ee.y, w.y, v.y);
                v.z = fmaf(ee.y, w.z, v.z); v.w = fmaf(ee.y, w.w, v.w);
            }

            unsigned m01 = h2_to_u(__floats2half2_rn(silu(v.x), silu(v.y)));
            unsigned m23 = h2_to_u(__floats2half2_rn(silu(v.z), silu(v.w)));
            __half* dst = g_aggHh + (size_t)c * 64 + hl * 4;
            asm volatile("red.global.add.noftz.v2.f16x2 [%0], {%1, %2};"
                         :: "l"(dst), "r"(m01), "r"(m23) : "memory");
        }
    }
}

// ---------------- fused node phase: paired-k weights (uint2) + float4 acts -----
// per 2 k-steps: 1 LDS128 (activation pairs) + 1 LDS64 (2 weight half2) + 8 FMA
__global__ void __launch_bounds__(256, 4)
k_node(const float* __restrict__ w2, const float* __restrict__ b2,
       const float* __restrict__ uw1, const float* __restrict__ ub1,
       const float* __restrict__ uw2, const float* __restrict__ ub2,
       const float* __restrict__ ew1, const float* __restrict__ eb1,
       const float* __restrict__ ew2, const float* __restrict__ eb2,
       const int* __restrict__ batch, float* __restrict__ out,
       int N, int do_readout) {
    extern __shared__ float sm[];
    uint2* uW2p  = (uint2*)sm;                    // 1024 uint2: [kp][lane], k=2kp,2kp+1
    uint2* uUW1p = uW2p + 1024;                   // 2048 uint2
    uint2* uUW2p = uUW1p + 2048;                  // 1024 uint2
    uint2* uEW1p = uUW2p + 1024;                  // 1024 uint2 (ends at 10240 words)
    float2* sb2v  = (float2*)(sm + 10240);        // 32 f2
    float2* sub1v = sb2v + 32;
    float2* sub2v = sub1v + 32;
    float2* seb1v = sub2v + 32;
    float2* sew2v = seb1v + 32;                   // ends at 10560 words
    float* sEb2 = sm + 10560;                     // 16 words pad
    float* sIn  = sm + 10576;                     // 8 warps * 256 (128 float2 pairs)
    float* sHid = sm + 12624;                     // 8 warps * 128 (64 float2 pairs)

    const float2* w2f = (const float2*)w2;
    const float2* uw1f = (const float2*)uw1;
    const float2* uw2f = (const float2*)uw2;
    const float2* ew1f = (const float2*)ew1;

    for (int u = threadIdx.x; u < 1024; u += blockDim.x) {
        int kp = u >> 5, l = u & 31;
        float2 f0 = w2f[(2 * kp) * 32 + l];
        float2 f1 = w2f[(2 * kp + 1) * 32 + l];
        uW2p[u] = make_uint2(h2_to_u(__floats2half2_rn(f0.x, f0.y)),
                             h2_to_u(__floats2half2_rn(f1.x, f1.y)));
    }
    for (int u = threadIdx.x; u < 2048; u += blockDim.x) {
        int kp = u >> 5, l = u & 31;
        float2 f0 = uw1f[(2 * kp) * 32 + l];
        float2 f1 = uw1f[(2 * kp + 1) * 32 + l];
        uUW1p[u] = make_uint2(h2_to_u(__floats2half2_rn(f0.x, f0.y)),
                              h2_to_u(__floats2half2_rn(f1.x, f1.y)));
    }
    for (int u = threadIdx.x; u < 1024; u += blockDim.x) {
        int kp = u >> 5, l = u & 31;
        float2 f0 = uw2f[(2 * kp) * 32 + l];
        float2 f1 = uw2f[(2 * kp + 1) * 32 + l];
        uUW2p[u] = make_uint2(h2_to_u(__floats2half2_rn(f0.x, f0.y)),
                              h2_to_u(__floats2half2_rn(f1.x, f1.y)));
    }
    if (do_readout) {
        for (int u = threadIdx.x; u < 1024; u += blockDim.x) {
            int kp = u >> 5, l = u & 31;
            float2 f0 = ew1f[(2 * kp) * 32 + l];
            float2 f1 = ew1f[(2 * kp + 1) * 32 + l];
            uEW1p[u] = make_uint2(h2_to_u(__floats2half2_rn(f0.x, f0.y)),
                                  h2_to_u(__floats2half2_rn(f1.x, f1.y)));
        }
    }
    if (threadIdx.x < 32) {
        sb2v[threadIdx.x]  = ((const float2*)b2)[threadIdx.x];
        sub1v[threadIdx.x] = ((const float2*)ub1)[threadIdx.x];
        sub2v[threadIdx.x] = ((const float2*)ub2)[threadIdx.x];
        if (do_readout) {
            seb1v[threadIdx.x] = ((const float2*)eb1)[threadIdx.x];
            sew2v[threadIdx.x] = ((const float2*)ew2)[threadIdx.x];
        }
    }
    if (threadIdx.x == 0) sEb2[0] = do_readout ? eb2[0] : 0.0f;
    __syncthreads();

    int warp = threadIdx.x >> 5, lane = threadIdx.x & 31;
    int gw = (blockIdx.x * blockDim.x + threadIdx.x) >> 5;
    int nw = (gridDim.x * blockDim.x) >> 5;
    float2* inP  = (float2*)(sIn + warp * 256);   // 128 pairs = 64 float4
    float2* hidP = (float2*)(sHid + warp * 128);  // 64 pairs = 32 float4
    const float4* inP4  = (const float4*)inP;
    const float4* hidP4 = (const float4*)hidP;

    const float2* X2r = (const float2*)g_x;
    float2* X2w = (float2*)g_x;
    const unsigned* AGH = (const unsigned*)g_aggHh;   // fp16x2 accumulators

    for (int r0 = gw * 2; r0 < N; r0 += nw * 2) {
        int nr = min(2, N - r0);

        // --- phase A: agg = aggH @ W2 + deg*b2 (paired k) ---
        {
            float2 ag0 = u_to_f2(AGH[(size_t)r0 * 32 + lane]);
            float2 ag1 = (nr > 1) ? u_to_f2(AGH[(size_t)(r0 + 1) * 32 + lane])
                                  : make_float2(0.f, 0.f);
            hidP[2 * lane]     = make_float2(ag0.x, ag1.x);
            hidP[2 * lane + 1] = make_float2(ag0.y, ag1.y);
        }
        __syncwarp();

        float2 agg[2] = {make_float2(0.f, 0.f), make_float2(0.f, 0.f)};
#pragma unroll 8
        for (int kp = 0; kp < 32; kp++) {
            float4 a2 = hidP4[kp];                    // (r0[2kp], r1[2kp], r0[2kp+1], r1[2kp+1])
            uint2 wu = uW2p[kp * 32 + lane];
            float2 b0 = u_to_f2(wu.x);
            float2 b1 = u_to_f2(wu.y);
            agg[0].x = fmaf(a2.x, b0.x, agg[0].x); agg[0].y = fmaf(a2.x, b0.y, agg[0].y);
            agg[1].x = fmaf(a2.y, b0.x, agg[1].x); agg[1].y = fmaf(a2.y, b0.y, agg[1].y);
            agg[0].x = fmaf(a2.z, b1.x, agg[0].x); agg[0].y = fmaf(a2.z, b1.y, agg[0].y);
            agg[1].x = fmaf(a2.w, b1.x, agg[1].x); agg[1].y = fmaf(a2.w, b1.y, agg[1].y);
        }
        float2 bb2 = sb2v[lane];
        float2 xp[2], nx[2];
        nx[0] = nx[1] = make_float2(0.f, 0.f);
#pragma unroll
        for (int rr = 0; rr < 2; rr++) {
            float dg = (rr < nr) ? g_deg[r0 + rr] : 0.0f;
            agg[rr].x = fmaf(dg, bb2.x, agg[rr].x);
            agg[rr].y = fmaf(dg, bb2.y, agg[rr].y);
            if (rr < nr) xp[rr] = X2r[(r0 + rr) * 32 + lane];
            else         xp[rr] = make_float2(0.f, 0.f);
        }
        __syncwarp();

        // --- phase B: stage [x, agg] interleaved ---
        inP[2 * lane]          = make_float2(xp[0].x, xp[1].x);
        inP[2 * lane + 1]      = make_float2(xp[0].y, xp[1].y);
        inP[64 + 2 * lane]     = make_float2(agg[0].x, agg[1].x);
        inP[64 + 2 * lane + 1] = make_float2(agg[0].y, agg[1].y);
        __syncwarp();

        // --- phase C: hidden = silu([x,agg]@uW1 + ub1) ---
        float2 ub1p = sub1v[lane];
        float2 acc[2] = {ub1p, ub1p};
#pragma unroll 8
        for (int kp = 0; kp < 64; kp++) {
            float4 a2 = inP4[kp];
            uint2 wu = uUW1p[kp * 32 + lane];
            float2 w0 = u_to_f2(wu.x);
            float2 w1 = u_to_f2(wu.y);
            acc[0].x = fmaf(a2.x, w0.x, acc[0].x); acc[0].y = fmaf(a2.x, w0.y, acc[0].y);
            acc[1].x = fmaf(a2.y, w0.x, acc[1].x); acc[1].y = fmaf(a2.y, w0.y, acc[1].y);
            acc[0].x = fmaf(a2.z, w1.x, acc[0].x); acc[0].y = fmaf(a2.z, w1.y, acc[0].y);
            acc[1].x = fmaf(a2.w, w1.x, acc[1].x); acc[1].y = fmaf(a2.w, w1.y, acc[1].y);
        }
        __syncwarp();
        hidP[2 * lane]     = make_float2(silu(acc[0].x), silu(acc[1].x));
        hidP[2 * lane + 1] = make_float2(silu(acc[0].y), silu(acc[1].y));
        __syncwarp();

        // --- phase D: o = hid@uW2 + ub2; x += o ---
        float2 ub2p = sub2v[lane];
        float2 o[2] = {ub2p, ub2p};
#pragma unroll 8
        for (int kp = 0; kp < 32; kp++) {
            float4 a2 = hidP4[kp];
            uint2 wu = uUW2p[kp * 32 + lane];
            float2 w0 = u_to_f2(wu.x);
            float2 w1 = u_to_f2(wu.y);
            o[0].x = fmaf(a2.x, w0.x, o[0].x); o[0].y = fmaf(a2.x, w0.y, o[0].y);
            o[1].x = fmaf(a2.y, w0.x, o[1].x); o[1].y = fmaf(a2.y, w0.y, o[1].y);
            o[0].x = fmaf(a2.z, w1.x, o[0].x); o[0].y = fmaf(a2.z, w1.y, o[0].y);
            o[1].x = fmaf(a2.w, w1.x, o[1].x); o[1].y = fmaf(a2.w, w1.y, o[1].y);
        }
        for (int rr = 0; rr < nr; rr++) {
            nx[rr].x = xp[rr].x + o[rr].x;
            nx[rr].y = xp[rr].y + o[rr].y;
            X2w[(r0 + rr) * 32 + lane] = nx[rr];
        }

        // --- phase E: readout (last layer only) ---
        if (do_readout) {
            __syncwarp();
            inP[2 * lane]     = make_float2(nx[0].x, nx[1].x);
            inP[2 * lane + 1] = make_float2(nx[0].y, nx[1].y);
            __syncwarp();
            float2 eb1p = seb1v[lane];
            float2 ec[2] = {eb1p, eb1p};
#pragma unroll 8
            for (int kp = 0; kp < 32; kp++) {
                float4 a2 = inP4[kp];
                uint2 wu = uEW1p[kp * 32 + lane];
                float2 w0 = u_to_f2(wu.x);
                float2 w1 = u_to_f2(wu.y);
                ec[0].x = fmaf(a2.x, w0.x, ec[0].x); ec[0].y = fmaf(a2.x, w0.y, ec[0].y);
                ec[1].x = fmaf(a2.y, w0.x, ec[1].x); ec[1].y = fmaf(a2.y, w0.y, ec[1].y);
                ec[0].x = fmaf(a2.z, w1.x, ec[0].x); ec[0].y = fmaf(a2.z, w1.y, ec[0].y);
                ec[1].x = fmaf(a2.w, w1.x, ec[1].x); ec[1].y = fmaf(a2.w, w1.y, ec[1].y);
            }
            float2 w2p = sew2v[lane];
            for (int rr = 0; rr < nr; rr++) {
                float pe = silu(ec[rr].x) * w2p.x + silu(ec[rr].y) * w2p.y;
#pragma unroll
                for (int off = 16; off > 0; off >>= 1)
                    pe += __shfl_xor_sync(0xFFFFFFFF, pe, off);
                if (lane == 0)
                    atomicAdd(&out[batch[r0 + rr]], pe + sEb2[0]);
            }
        }
        __syncwarp();
    }
}

// ------------------------------- host side ------------------------------------
extern "C" void kernel_launch(void* const* d_in, const int* in_sizes, int n_in,
                              void* d_out, int out_size) {
    const int* z = (const int*)d_in[0];
    const float* pos = (const float*)d_in[1];
    const int* ei = (const int*)d_in[2];
    const int* batch = (const int*)d_in[3];
    const float* embed = (const float*)d_in[4];
    const float* msg_w1 = (const float*)d_in[5];
    const float* msg_b1 = (const float*)d_in[6];
    const float* msg_w2 = (const float*)d_in[7];
    const float* msg_b2 = (const float*)d_in[8];
    const float* upd_w1 = (const float*)d_in[9];
    const float* upd_b1 = (const float*)d_in[10];
    const float* upd_w2 = (const float*)d_in[11];
    const float* upd_b2 = (const float*)d_in[12];
    const float* eh_w1 = (const float*)d_in[13];
    const float* eh_b1 = (const float*)d_in[14];
    const float* eh_w2 = (const float*)d_in[15];
    const float* eh_b2 = (const float*)d_in[16];
    float* out = (float*)d_out;

    int N = in_sizes[0];
    int E = in_sizes[2] / 2;

    float* p_deg; cudaGetSymbolAddress((void**)&p_deg, g_deg);

    static bool init_done = false;
    if (!init_done) {
        cudaFuncSetAttribute(k_node, cudaFuncAttributeMaxDynamicSharedMemorySize, 13648 * 4);
        init_done = true;
    }

    const int TPB = 256;
    const int PQB  = 148 * 6;   // one full resident wave for k_pq (6 blocks/SM)
    const int EBLK = 148 * 8;   // one full resident wave for k_edge (8 blocks/SM)
    const int NODB = 148 * 4;   // one full resident wave for k_node (4 blocks/SM)

    // prologue (sequential — stream fork measured as a regression in R15)
    k_prep<<<256, TPB>>>(pos, N, p_deg, out, out_size);
    k_edge_attr<<<1184, TPB>>>(ei, E);

    for (int l = 0; l < NL; l++) {
        const float* w1 = msg_w1 + l * 136 * 64;
        const float* b1 = msg_b1 + l * 64;
        const float* w2 = msg_w2 + l * 64 * 64;
        const float* b2 = msg_b2 + l * 64;
        const float* uw1 = upd_w1 + l * 128 * 64;
        const float* ub1 = upd_b1 + l * 64;
        const float* uw2 = upd_w2 + l * 64 * 64;
        const float* ub2 = upd_b2 + l * 64;

        k_pq<<<PQB, TPB>>>(w1, b1, (l == 0) ? z : nullptr,
                           (l == 0) ? embed : nullptr, N);
        k_edge<<<EBLK, TPB>>>(w1, E);
        k_node<<<NODB, TPB, 13648 * 4>>>(w2, b2, uw1, ub1, uw2, ub2,
                                         eh_w1, eh_b1, eh_w2, eh_b2,
                                         batch, out, N, (l == NL - 1) ? 1 : 0);
    }
}